// round 16
// baseline (speedup 1.0000x reference)
#include <cuda_runtime.h>
#include <cuda_bf16.h>
#include <mma.h>
#include <math.h>

using namespace nvcuda;

#define NN 50000
#define EE 800000
#define DD 128
#define CSR_GRID 200

// ---------------- scratch (device globals; allocation-free rule) ----------------
__device__ int   g_deg[NN];
__device__ int   g_rowptr[NN + 1];
__device__ int   g_cursor[NN];
__device__ int   g_cols[EE];
__device__ float g_dis[NN];
__device__ int   g_bsum[256];
__device__ int   g_boff[256];
__device__ __align__(16) float g_h[NN * DD];
__device__ __align__(16) float g_agg[NN * DD];
__device__ __align__(16) float g_x[NN * DD];
__device__ float g_stats[3 * 2 * DD];   // per-layer: sum / sumsq
__device__ __align__(16) __nv_bfloat16 g_Whi[3 * DD * DD];
__device__ __align__(16) __nv_bfloat16 g_Wlo[3 * DD * DD];
__device__ int   g_bar_count;
__device__ volatile int g_bar_phase;

// ---------------- grid barrier (sense-reversing, bounded spin) ----------------
__device__ __forceinline__ void grid_bar() {
    __syncthreads();
    if (threadIdx.x == 0) {
        int gen = g_bar_phase;
        __threadfence();
        if (atomicAdd(&g_bar_count, 1) == (int)gridDim.x - 1) {
            g_bar_count = 0;
            __threadfence();
            g_bar_phase = gen + 1;
        } else {
            for (int t = 0; t < (1 << 22) && g_bar_phase == gen; ++t) { }
        }
    }
    __syncthreads();
}

// ---------------- fused CSR build: zero + degree + scan + apply + fill ----------------
__global__ __launch_bounds__(256) void csr_build_kernel(const int* __restrict__ src,
                                                        const int* __restrict__ dst,
                                                        int n, int e) {
    __shared__ int wsum[8];
    int tid = threadIdx.x;
    int lane = tid & 31, wid = tid >> 5;
    int gtid = blockIdx.x * 256 + tid;
    int gsz = gridDim.x * 256;
    int nb = (n + 255) / 256;

    for (int i = gtid; i < n; i += gsz) g_deg[i] = 0;
    for (int i = gtid; i < 3 * 2 * DD; i += gsz) g_stats[i] = 0.0f;
    grid_bar();

    for (int i = gtid; i < e; i += gsz) atomicAdd(&g_deg[dst[i]], 1);
    grid_bar();

    for (int b = blockIdx.x; b < nb; b += gridDim.x) {
        __syncthreads();
        int i = b * 256 + tid;
        int v = (i < n) ? g_deg[i] : 0;
        int incl = v;
        #pragma unroll
        for (int off = 1; off < 32; off <<= 1) {
            int t = __shfl_up_sync(0xffffffffu, incl, off);
            if (lane >= off) incl += t;
        }
        if (lane == 31) wsum[wid] = incl;
        __syncthreads();
        if (wid == 0 && lane < 8) {
            int w = wsum[lane];
            int s = w;
            #pragma unroll
            for (int off = 1; off < 8; off <<= 1) {
                int t = __shfl_up_sync(0xffu, s, off);
                if (lane >= off) s += t;
            }
            wsum[lane] = s - w;
        }
        __syncthreads();
        int excl = incl - v + wsum[wid];
        if (i < n) g_rowptr[i] = excl;
        if (tid == 255) g_bsum[b] = excl + v;
    }
    grid_bar();

    if (blockIdx.x == 0) {
        int v = (tid < nb) ? g_bsum[tid] : 0;
        int incl = v;
        #pragma unroll
        for (int off = 1; off < 32; off <<= 1) {
            int t = __shfl_up_sync(0xffffffffu, incl, off);
            if (lane >= off) incl += t;
        }
        if (lane == 31) wsum[wid] = incl;
        __syncthreads();
        if (wid == 0 && lane < 8) {
            int w = wsum[lane];
            int s = w;
            #pragma unroll
            for (int off = 1; off < 8; off <<= 1) {
                int t = __shfl_up_sync(0xffu, s, off);
                if (lane >= off) s += t;
            }
            wsum[lane] = s - w;
        }
        __syncthreads();
        int excl = incl - v + wsum[wid];
        if (tid < nb) g_boff[tid] = excl;
        if (tid == nb - 1) g_rowptr[n] = excl + v;
    }
    grid_bar();

    for (int b = blockIdx.x; b < nb; b += gridDim.x) {
        int i = b * 256 + tid;
        if (i < n) {
            int excl = g_rowptr[i] + g_boff[b];
            g_rowptr[i] = excl;
            g_cursor[i] = excl;
            g_dis[i] = rsqrtf((float)g_deg[i] + 1.0f);
        }
    }
    grid_bar();

    for (int i = gtid; i < e; i += gsz) {
        int d = dst[i];
        int pos = atomicAdd(&g_cursor[d], 1);
        g_cols[pos] = src[i];
    }
}

// ---------------- W precompute: fp32 -> hi/lo bf16 for all 3 layers ----------------
__global__ __launch_bounds__(256) void wconv_kernel(const float* __restrict__ Ws) {
    int i = blockIdx.x * blockDim.x + threadIdx.x;
    if (i < 3 * DD * DD) {
        float v = Ws[i];
        __nv_bfloat16 h = __float2bfloat16(v);
        __nv_bfloat16 l = __float2bfloat16(v - __bfloat162float(h));
        g_Whi[i] = h;
        g_Wlo[i] = l;
    }
}

// ---------------- WMMA GEMM: g_h = (dis .* X) @ W, split-bf16 x3 products ----------------
// block 256 threads (8 warps), M-tile 128 (warp w -> rows w*16..+15), N = 128 (8 n-tiles).
// K chunked by 64 (4 ks of 16). X staged warp-private (NO block syncs in main loop).
// B fragments loaded DIRECTLY from global precomputed bf16 W (L1-resident).
// mode 0: X = Xext. mode 1: v = relu(bn_prev(agg)) (+ g_x if residual); g_x = v; X = v.
#define A_STRIDE 72   // 64 + 8 pad, bf16 elems

__global__ __launch_bounds__(256) void gemm_wmma_kernel(const float* __restrict__ Xext,
                                                        const __nv_bfloat16* __restrict__ Wh,
                                                        const __nv_bfloat16* __restrict__ Wl,
                                                        const float* __restrict__ gamma_prev,
                                                        const float* __restrict__ beta_prev,
                                                        int n, int mode, int residual,
                                                        int layer, float invn) {
    __shared__ __align__(16) __nv_bfloat16 As_hi[128 * A_STRIDE];
    __shared__ __align__(16) __nv_bfloat16 As_lo[128 * A_STRIDE];
    __shared__ float sscale[DD];
    __shared__ float sshift[DD];
    __shared__ __align__(16) float pscratch[16 * 20];

    int tid = threadIdx.x;
    int warp = tid >> 5;
    int lane = tid & 31;
    int m0 = blockIdx.x * 128;

    if (mode == 1) {
        if (tid < DD) {
            int base = (layer - 1) * 2 * DD;
            float s  = g_stats[base + tid];
            float sq = g_stats[base + DD + tid];
            float mean = s * invn;
            float var  = sq * invn - mean * mean;
            float istd = rsqrtf(var + 1e-5f);
            float sc = gamma_prev[tid] * istd;
            sscale[tid] = sc;
            sshift[tid] = beta_prev[tid] - mean * sc;
        }
        __syncthreads();
    }

    wmma::fragment<wmma::accumulator, 16, 16, 16, float> acc[8];
    #pragma unroll
    for (int nt = 0; nt < 8; nt++) wmma::fill_fragment(acc[nt], 0.0f);

    for (int kc = 0; kc < 128; kc += 64) {
        // ---- warp-private X staging: warp converts its OWN 16 rows x 64 k ----
        // 16 rows x 16 float4/row = 256 float4 -> 8 per lane
        #pragma unroll
        for (int i = 0; i < 8; i++) {
            int f = lane + 32 * i;
            int rl = f >> 4, k4 = f & 15;
            int row = m0 + warp * 16 + rl;
            float4 v = make_float4(0.f, 0.f, 0.f, 0.f);
            float dn = 0.0f;
            if (row < n) {
                dn = g_dis[row];
                int idx = row * 128 + kc + k4 * 4;
                if (mode == 0) {
                    v = *(const float4*)&Xext[idx];
                } else {
                    float4 a = *(const float4*)&g_agg[idx];
                    int c = kc + k4 * 4;
                    v.x = fmaxf(a.x * sscale[c + 0] + sshift[c + 0], 0.f);
                    v.y = fmaxf(a.y * sscale[c + 1] + sshift[c + 1], 0.f);
                    v.z = fmaxf(a.z * sscale[c + 2] + sshift[c + 2], 0.f);
                    v.w = fmaxf(a.w * sscale[c + 3] + sshift[c + 3], 0.f);
                    if (residual) {
                        float4 rr = *(const float4*)&g_x[idx];
                        v.x += rr.x; v.y += rr.y; v.z += rr.z; v.w += rr.w;
                    }
                    *(float4*)&g_x[idx] = v;
                }
            }
            float s0 = v.x * dn, s1 = v.y * dn, s2 = v.z * dn, s3 = v.w * dn;
            __nv_bfloat16 h0 = __float2bfloat16(s0);
            __nv_bfloat16 h1 = __float2bfloat16(s1);
            __nv_bfloat16 h2 = __float2bfloat16(s2);
            __nv_bfloat16 h3 = __float2bfloat16(s3);
            __nv_bfloat162 hp0 = __nv_bfloat162(h0, h1);
            __nv_bfloat162 hp1 = __nv_bfloat162(h2, h3);
            __nv_bfloat162 lp0 = __nv_bfloat162(__float2bfloat16(s0 - __bfloat162float(h0)),
                                                __float2bfloat16(s1 - __bfloat162float(h1)));
            __nv_bfloat162 lp1 = __nv_bfloat162(__float2bfloat16(s2 - __bfloat162float(h2)),
                                                __float2bfloat16(s3 - __bfloat162float(h3)));
            int base = (warp * 16 + rl) * A_STRIDE + k4 * 4;
            *(__nv_bfloat162*)&As_hi[base]     = hp0;
            *(__nv_bfloat162*)&As_hi[base + 2] = hp1;
            *(__nv_bfloat162*)&As_lo[base]     = lp0;
            *(__nv_bfloat162*)&As_lo[base + 2] = lp1;
        }
        __syncwarp();

        // ---- MMA: 4 ks x 8 nt x 3 products; B direct from global (L1-hot) ----
        #pragma unroll
        for (int ks = 0; ks < 4; ks++) {
            wmma::fragment<wmma::matrix_a, 16, 16, 16, __nv_bfloat16, wmma::row_major> a_hi, a_lo;
            wmma::load_matrix_sync(a_hi, &As_hi[(warp * 16) * A_STRIDE + ks * 16], A_STRIDE);
            wmma::load_matrix_sync(a_lo, &As_lo[(warp * 16) * A_STRIDE + ks * 16], A_STRIDE);
            int krow = kc + ks * 16;
            #pragma unroll
            for (int nt = 0; nt < 8; nt++) {
                wmma::fragment<wmma::matrix_b, 16, 16, 16, __nv_bfloat16, wmma::row_major> b_hi, b_lo;
                wmma::load_matrix_sync(b_hi, &Wh[krow * 128 + nt * 16], 128);
                wmma::load_matrix_sync(b_lo, &Wl[krow * 128 + nt * 16], 128);
                wmma::mma_sync(acc[nt], a_hi, b_hi, acc[nt]);
                wmma::mma_sync(acc[nt], a_lo, b_hi, acc[nt]);
                wmma::mma_sync(acc[nt], a_hi, b_lo, acc[nt]);
            }
        }
        __syncwarp();
    }

    // ---- epilogue: store fragments straight to g_h (dis already applied) ----
    int row_base = m0 + warp * 16;
    if (row_base + 16 <= n) {
        #pragma unroll
        for (int nt = 0; nt < 8; nt++) {
            wmma::store_matrix_sync(&g_h[row_base * 128 + nt * 16], acc[nt], 128,
                                    wmma::mem_row_major);
        }
    } else if (row_base < n) {
        for (int w = 0; w < 8; w++) {
            if (warp == w && row_base < n) {
                int nvalid = n - row_base;
                for (int nt = 0; nt < 8; nt++) {
                    wmma::store_matrix_sync(pscratch, acc[nt], 20, wmma::mem_row_major);
                    __syncwarp();
                    for (int el = lane; el < nvalid * 16; el += 32) {
                        int rr = el >> 4, cc = el & 15;
                        g_h[(row_base + rr) * 128 + nt * 16 + cc] = pscratch[rr * 20 + cc];
                    }
                    __syncwarp();
                }
            }
            __syncthreads();
        }
    }
}

// ---------------- Aggregation (warp/node) + per-layer BN stat partials ----------------
__global__ __launch_bounds__(256) void agg_kernel(const float* __restrict__ bias, int n,
                                                  int layer) {
    __shared__ float red[8][256];
    int tid = threadIdx.x;
    int lane = tid & 31, wid = tid >> 5;
    float4 bv = *(const float4*)&bias[lane * 4];

    float ls0 = 0.f, ls1 = 0.f, ls2 = 0.f, ls3 = 0.f;
    float lq0 = 0.f, lq1 = 0.f, lq2 = 0.f, lq3 = 0.f;

    for (int node = blockIdx.x * 8 + wid; node < n; node += gridDim.x * 8) {
        int beg = __ldg(&g_rowptr[node]);
        int end = __ldg(&g_rowptr[node + 1]);
        float ax = 0.f, ay = 0.f, az = 0.f, aw = 0.f;
        int j = beg;
        for (; j + 3 < end; j += 4) {
            int c0 = __ldg(&g_cols[j]);
            int c1 = __ldg(&g_cols[j + 1]);
            int c2 = __ldg(&g_cols[j + 2]);
            int c3 = __ldg(&g_cols[j + 3]);
            float4 h0 = *(const float4*)&g_h[c0 * 128 + lane * 4];
            float4 h1 = *(const float4*)&g_h[c1 * 128 + lane * 4];
            float4 h2 = *(const float4*)&g_h[c2 * 128 + lane * 4];
            float4 h3 = *(const float4*)&g_h[c3 * 128 + lane * 4];
            ax += h0.x + h1.x + h2.x + h3.x;
            ay += h0.y + h1.y + h2.y + h3.y;
            az += h0.z + h1.z + h2.z + h3.z;
            aw += h0.w + h1.w + h2.w + h3.w;
        }
        for (; j < end; j++) {
            int c0 = __ldg(&g_cols[j]);
            float4 h0 = *(const float4*)&g_h[c0 * 128 + lane * 4];
            ax += h0.x; ay += h0.y; az += h0.z; aw += h0.w;
        }
        float4 hs = *(const float4*)&g_h[node * 128 + lane * 4];
        float dn = __ldg(&g_dis[node]);
        ax = dn * (ax + hs.x) + bv.x;
        ay = dn * (ay + hs.y) + bv.y;
        az = dn * (az + hs.z) + bv.z;
        aw = dn * (aw + hs.w) + bv.w;
        *(float4*)&g_agg[node * 128 + lane * 4] = make_float4(ax, ay, az, aw);

        ls0 += ax; ls1 += ay; ls2 += az; ls3 += aw;
        lq0 += ax * ax; lq1 += ay * ay; lq2 += az * az; lq3 += aw * aw;
    }

    int sbase = layer * 2 * DD;
    red[wid][lane * 4 + 0] = ls0;
    red[wid][lane * 4 + 1] = ls1;
    red[wid][lane * 4 + 2] = ls2;
    red[wid][lane * 4 + 3] = ls3;
    __syncthreads();
    float tot = 0.f;
    #pragma unroll
    for (int w = 0; w < 8; w++) tot += red[w][tid];
    if (tid < 128) atomicAdd(&g_stats[sbase + tid], tot);
    __syncthreads();
    red[wid][lane * 4 + 0] = lq0;
    red[wid][lane * 4 + 1] = lq1;
    red[wid][lane * 4 + 2] = lq2;
    red[wid][lane * 4 + 3] = lq3;
    __syncthreads();
    tot = 0.f;
    #pragma unroll
    for (int w = 0; w < 8; w++) tot += red[w][tid];
    if (tid < 128) atomicAdd(&g_stats[sbase + DD + tid], tot);
}

// ---------------- Final elementwise: out = x2 + bn_2(agg2), no relu ----------------
__global__ __launch_bounds__(256) void elem_final_kernel(float* __restrict__ out,
                                                         const float* __restrict__ gamma,
                                                         const float* __restrict__ beta,
                                                         int n4, float invn) {
    __shared__ float sscale[DD];
    __shared__ float sshift[DD];
    int tid = threadIdx.x;
    if (tid < DD) {
        int base = 2 * 2 * DD;
        float s  = g_stats[base + tid];
        float sq = g_stats[base + DD + tid];
        float mean = s * invn;
        float var  = sq * invn - mean * mean;
        float istd = rsqrtf(var + 1e-5f);
        float sc = gamma[tid] * istd;
        sscale[tid] = sc;
        sshift[tid] = beta[tid] - mean * sc;
    }
    __syncthreads();

    int idx = blockIdx.x * blockDim.x + tid;
    if (idx >= n4) return;
    int c4 = idx & 31;
    float4 sc = ((const float4*)sscale)[c4];
    float4 sh = ((const float4*)sshift)[c4];
    float4 a  = ((const float4*)g_agg)[idx];
    float4 r  = ((const float4*)g_x)[idx];
    float4 y;
    y.x = a.x * sc.x + sh.x + r.x;
    y.y = a.y * sc.y + sh.y + r.y;
    y.z = a.z * sc.z + sh.z + r.z;
    y.w = a.w * sc.w + sh.w + r.w;
    ((float4*)out)[idx] = y;
}

// ---------------- launch ----------------
extern "C" void kernel_launch(void* const* d_in, const int* in_sizes, int n_in,
                              void* d_out, int out_size) {
    const float* x      = (const float*)d_in[0];
    const int*   ei     = (const int*)d_in[1];
    const float* Ws     = (const float*)d_in[2];
    const float* bs     = (const float*)d_in[3];
    const float* gammas = (const float*)d_in[4];
    const float* betas  = (const float*)d_in[5];

    int n = in_sizes[0] / DD;   // 50000
    int e = in_sizes[1] / 2;    // 800000
    const int* src = ei;
    const int* dst = ei + e;

    csr_build_kernel<<<CSR_GRID, 256>>>(src, dst, n, e);
    wconv_kernel<<<(3 * DD * DD + 255) / 256, 256>>>(Ws);

    float invn = 1.0f / (float)n;
    int n4 = n * (DD / 4);
    int gemm_grid = (n + 127) / 128;
    int agg_grid = 1184;

    // device-global pointers for W hi/lo
    __nv_bfloat16 *wh_ptr, *wl_ptr;
    cudaGetSymbolAddress((void**)&wh_ptr, g_Whi);
    cudaGetSymbolAddress((void**)&wl_ptr, g_Wlo);

    for (int l = 0; l < 3; l++) {
        int mode = (l > 0) ? 1 : 0;
        int residual = (l > 1) ? 1 : 0;
        const float* gprev = gammas + (l > 0 ? (l - 1) : 0) * DD;
        const float* bprev = betas + (l > 0 ? (l - 1) : 0) * DD;
        gemm_wmma_kernel<<<gemm_grid, 256>>>(x, wh_ptr + l * DD * DD, wl_ptr + l * DD * DD,
                                             gprev, bprev, n, mode, residual, l, invn);
        agg_kernel<<<agg_grid, 256>>>(bs + l * DD, n, l);
    }
    elem_final_kernel<<<(n4 + 255) / 256, 256>>>((float*)d_out, gammas + 2 * DD,
                                                 betas + 2 * DD, n4, invn);
}

// round 17
// speedup vs baseline: 1.3998x; 1.3998x over previous
#include <cuda_runtime.h>
#include <cuda_bf16.h>
#include <mma.h>
#include <math.h>

using namespace nvcuda;

#define NN 50000
#define EE 800000
#define DD 128
#define CSR_GRID 200

// ---------------- scratch (device globals; allocation-free rule) ----------------
__device__ int   g_deg[NN];
__device__ int   g_rowptr[NN + 1];
__device__ int   g_cursor[NN];
__device__ int   g_cols[EE];
__device__ float g_dis[NN];
__device__ int   g_bsum[256];
__device__ int   g_boff[256];
__device__ __align__(16) float g_h[NN * DD];
__device__ __align__(16) float g_agg[NN * DD];
__device__ __align__(16) float g_x[NN * DD];
__device__ float g_stats[3 * 2 * DD];   // per-layer: sum / sumsq
__device__ __align__(16) __nv_bfloat16 g_Whi[3 * DD * DD];
__device__ __align__(16) __nv_bfloat16 g_Wlo[3 * DD * DD];
__device__ int   g_bar_count;
__device__ volatile int g_bar_phase;

// ---------------- grid barrier (sense-reversing, bounded spin) ----------------
__device__ __forceinline__ void grid_bar() {
    __syncthreads();
    if (threadIdx.x == 0) {
        int gen = g_bar_phase;
        __threadfence();
        if (atomicAdd(&g_bar_count, 1) == (int)gridDim.x - 1) {
            g_bar_count = 0;
            __threadfence();
            g_bar_phase = gen + 1;
        } else {
            for (int t = 0; t < (1 << 22) && g_bar_phase == gen; ++t) { }
        }
    }
    __syncthreads();
}

// ---------------- fused CSR build: zero + degree + scan + apply + fill ----------------
__global__ __launch_bounds__(256) void csr_build_kernel(const int* __restrict__ src,
                                                        const int* __restrict__ dst,
                                                        int n, int e) {
    __shared__ int wsum[8];
    int tid = threadIdx.x;
    int lane = tid & 31, wid = tid >> 5;
    int gtid = blockIdx.x * 256 + tid;
    int gsz = gridDim.x * 256;
    int nb = (n + 255) / 256;

    for (int i = gtid; i < n; i += gsz) g_deg[i] = 0;
    for (int i = gtid; i < 3 * 2 * DD; i += gsz) g_stats[i] = 0.0f;
    grid_bar();

    for (int i = gtid; i < e; i += gsz) atomicAdd(&g_deg[dst[i]], 1);
    grid_bar();

    for (int b = blockIdx.x; b < nb; b += gridDim.x) {
        __syncthreads();
        int i = b * 256 + tid;
        int v = (i < n) ? g_deg[i] : 0;
        int incl = v;
        #pragma unroll
        for (int off = 1; off < 32; off <<= 1) {
            int t = __shfl_up_sync(0xffffffffu, incl, off);
            if (lane >= off) incl += t;
        }
        if (lane == 31) wsum[wid] = incl;
        __syncthreads();
        if (wid == 0 && lane < 8) {
            int w = wsum[lane];
            int s = w;
            #pragma unroll
            for (int off = 1; off < 8; off <<= 1) {
                int t = __shfl_up_sync(0xffu, s, off);
                if (lane >= off) s += t;
            }
            wsum[lane] = s - w;
        }
        __syncthreads();
        int excl = incl - v + wsum[wid];
        if (i < n) g_rowptr[i] = excl;
        if (tid == 255) g_bsum[b] = excl + v;
    }
    grid_bar();

    if (blockIdx.x == 0) {
        int v = (tid < nb) ? g_bsum[tid] : 0;
        int incl = v;
        #pragma unroll
        for (int off = 1; off < 32; off <<= 1) {
            int t = __shfl_up_sync(0xffffffffu, incl, off);
            if (lane >= off) incl += t;
        }
        if (lane == 31) wsum[wid] = incl;
        __syncthreads();
        if (wid == 0 && lane < 8) {
            int w = wsum[lane];
            int s = w;
            #pragma unroll
            for (int off = 1; off < 8; off <<= 1) {
                int t = __shfl_up_sync(0xffu, s, off);
                if (lane >= off) s += t;
            }
            wsum[lane] = s - w;
        }
        __syncthreads();
        int excl = incl - v + wsum[wid];
        if (tid < nb) g_boff[tid] = excl;
        if (tid == nb - 1) g_rowptr[n] = excl + v;
    }
    grid_bar();

    for (int b = blockIdx.x; b < nb; b += gridDim.x) {
        int i = b * 256 + tid;
        if (i < n) {
            int excl = g_rowptr[i] + g_boff[b];
            g_rowptr[i] = excl;
            g_cursor[i] = excl;
            g_dis[i] = rsqrtf((float)g_deg[i] + 1.0f);
        }
    }
    grid_bar();

    for (int i = gtid; i < e; i += gsz) {
        int d = dst[i];
        int pos = atomicAdd(&g_cursor[d], 1);
        g_cols[pos] = src[i];
    }
}

// ---------------- W precompute: fp32 -> hi/lo bf16 for all 3 layers ----------------
__global__ __launch_bounds__(256) void wconv_kernel(const float* __restrict__ Ws) {
    int i = blockIdx.x * blockDim.x + threadIdx.x;
    if (i < 3 * DD * DD) {
        float v = Ws[i];
        __nv_bfloat16 h = __float2bfloat16(v);
        __nv_bfloat16 l = __float2bfloat16(v - __bfloat162float(h));
        g_Whi[i] = h;
        g_Wlo[i] = l;
    }
}

// ---------------- WMMA GEMM: g_h = (dis .* X) @ W, split-bf16 x3 products ----------------
// block 128 threads (4 warps). M-tile 64 (warp w -> rows w*16..+15), N = 128 (8 n-tiles).
// K chunked by 32 (2 k-steps of 16). W tiles COPIED pre-converted bf16 (uint4), smem-shared.
// dis folded into X conversion; accumulators stored directly to g_h.
// mode 0: X = Xext. mode 1: v = relu(bn_prev(agg)) (+ g_x if residual); g_x = v; X = v.
#define A_STRIDE 40    // 32 + 8 pad, bf16 elems
#define W_STRIDE 136   // 128 + 8 pad, bf16 elems

__global__ __launch_bounds__(128) void gemm_wmma_kernel(const float* __restrict__ Xext,
                                                        const __nv_bfloat16* __restrict__ Wh,
                                                        const __nv_bfloat16* __restrict__ Wl,
                                                        const float* __restrict__ gamma_prev,
                                                        const float* __restrict__ beta_prev,
                                                        int n, int mode, int residual,
                                                        int layer, float invn) {
    __shared__ __align__(16) __nv_bfloat16 As_hi[64 * A_STRIDE];
    __shared__ __align__(16) __nv_bfloat16 As_lo[64 * A_STRIDE];
    __shared__ __align__(16) __nv_bfloat16 Ws_hi[32 * W_STRIDE];
    __shared__ __align__(16) __nv_bfloat16 Ws_lo[32 * W_STRIDE];
    __shared__ float sscale[DD];
    __shared__ float sshift[DD];
    __shared__ __align__(16) float pscratch[16 * 20];

    int tid = threadIdx.x;
    int warp = tid >> 5;
    int m0 = blockIdx.x * 64;

    if (mode == 1) {
        if (tid < DD) {
            int base = (layer - 1) * 2 * DD;
            float s  = g_stats[base + tid];
            float sq = g_stats[base + DD + tid];
            float mean = s * invn;
            float var  = sq * invn - mean * mean;
            float istd = rsqrtf(var + 1e-5f);
            float sc = gamma_prev[tid] * istd;
            sscale[tid] = sc;
            sshift[tid] = beta_prev[tid] - mean * sc;
        }
        __syncthreads();
    }

    wmma::fragment<wmma::accumulator, 16, 16, 16, float> acc[8];
    #pragma unroll
    for (int nt = 0; nt < 8; nt++) wmma::fill_fragment(acc[nt], 0.0f);

    for (int kc = 0; kc < 128; kc += 32) {
        // ---- X chunk (64 rows x 32 k): fp32 -> dis-scaled hi/lo bf16, packed stores ----
        #pragma unroll
        for (int i = 0; i < 4; i++) {
            int f = tid + 128 * i;          // float4 index: 8 per row, 64 rows
            int r = f >> 3, k4 = f & 7;
            int row = m0 + r;
            float4 v = make_float4(0.f, 0.f, 0.f, 0.f);
            float dn = 0.0f;
            if (row < n) {
                dn = g_dis[row];
                int idx = row * 128 + kc + k4 * 4;
                if (mode == 0) {
                    v = *(const float4*)&Xext[idx];
                } else {
                    float4 a = *(const float4*)&g_agg[idx];
                    int c = kc + k4 * 4;
                    v.x = fmaxf(a.x * sscale[c + 0] + sshift[c + 0], 0.f);
                    v.y = fmaxf(a.y * sscale[c + 1] + sshift[c + 1], 0.f);
                    v.z = fmaxf(a.z * sscale[c + 2] + sshift[c + 2], 0.f);
                    v.w = fmaxf(a.w * sscale[c + 3] + sshift[c + 3], 0.f);
                    if (residual) {
                        float4 rr = *(const float4*)&g_x[idx];
                        v.x += rr.x; v.y += rr.y; v.z += rr.z; v.w += rr.w;
                    }
                    *(float4*)&g_x[idx] = v;
                }
            }
            float s0 = v.x * dn, s1 = v.y * dn, s2 = v.z * dn, s3 = v.w * dn;
            __nv_bfloat16 h0 = __float2bfloat16(s0);
            __nv_bfloat16 h1 = __float2bfloat16(s1);
            __nv_bfloat16 h2 = __float2bfloat16(s2);
            __nv_bfloat16 h3 = __float2bfloat16(s3);
            __nv_bfloat162 hp0 = __nv_bfloat162(h0, h1);
            __nv_bfloat162 hp1 = __nv_bfloat162(h2, h3);
            __nv_bfloat162 lp0 = __nv_bfloat162(__float2bfloat16(s0 - __bfloat162float(h0)),
                                                __float2bfloat16(s1 - __bfloat162float(h1)));
            __nv_bfloat162 lp1 = __nv_bfloat162(__float2bfloat16(s2 - __bfloat162float(h2)),
                                                __float2bfloat16(s3 - __bfloat162float(h3)));
            int base = r * A_STRIDE + k4 * 4;
            *(__nv_bfloat162*)&As_hi[base]     = hp0;
            *(__nv_bfloat162*)&As_hi[base + 2] = hp1;
            *(__nv_bfloat162*)&As_lo[base]     = lp0;
            *(__nv_bfloat162*)&As_lo[base + 2] = lp1;
        }
        // ---- W chunk (32 k x 128 n): raw bf16 copy, uint4 (8 bf16 each) ----
        // 32 rows x 16 uint4/row = 512 uint4 per tile; 4 per thread per tile
        #pragma unroll
        for (int i = 0; i < 4; i++) {
            int f = tid + 128 * i;
            int r = f >> 4, c8 = f & 15;
            uint4 vh = *(const uint4*)&Wh[(kc + r) * 128 + c8 * 8];
            uint4 vl = *(const uint4*)&Wl[(kc + r) * 128 + c8 * 8];
            *(uint4*)&Ws_hi[r * W_STRIDE + c8 * 8] = vh;
            *(uint4*)&Ws_lo[r * W_STRIDE + c8 * 8] = vl;
        }
        __syncthreads();

        // ---- MMA: 2 k-steps x 8 n-tiles x 3 products ----
        #pragma unroll
        for (int ks = 0; ks < 2; ks++) {
            wmma::fragment<wmma::matrix_a, 16, 16, 16, __nv_bfloat16, wmma::row_major> a_hi, a_lo;
            wmma::load_matrix_sync(a_hi, &As_hi[(warp * 16) * A_STRIDE + ks * 16], A_STRIDE);
            wmma::load_matrix_sync(a_lo, &As_lo[(warp * 16) * A_STRIDE + ks * 16], A_STRIDE);
            #pragma unroll
            for (int nt = 0; nt < 8; nt++) {
                wmma::fragment<wmma::matrix_b, 16, 16, 16, __nv_bfloat16, wmma::row_major> b_hi, b_lo;
                wmma::load_matrix_sync(b_hi, &Ws_hi[(ks * 16) * W_STRIDE + nt * 16], W_STRIDE);
                wmma::load_matrix_sync(b_lo, &Ws_lo[(ks * 16) * W_STRIDE + nt * 16], W_STRIDE);
                wmma::mma_sync(acc[nt], a_hi, b_hi, acc[nt]);
                wmma::mma_sync(acc[nt], a_lo, b_hi, acc[nt]);
                wmma::mma_sync(acc[nt], a_hi, b_lo, acc[nt]);
            }
        }
        __syncthreads();
    }

    // ---- epilogue: store fragments straight to g_h (dis already applied) ----
    int row_base = m0 + warp * 16;
    if (row_base + 16 <= n) {
        #pragma unroll
        for (int nt = 0; nt < 8; nt++) {
            wmma::store_matrix_sync(&g_h[row_base * 128 + nt * 16], acc[nt], 128,
                                    wmma::mem_row_major);
        }
    } else if (row_base < n) {
        for (int w = 0; w < 4; w++) {
            if (warp == w) {
                int nvalid = n - row_base;
                for (int nt = 0; nt < 8; nt++) {
                    wmma::store_matrix_sync(pscratch, acc[nt], 20, wmma::mem_row_major);
                    __syncwarp();
                    int lane = tid & 31;
                    for (int el = lane; el < nvalid * 16; el += 32) {
                        int rr = el >> 4, cc = el & 15;
                        g_h[(row_base + rr) * 128 + nt * 16 + cc] = pscratch[rr * 20 + cc];
                    }
                    __syncwarp();
                }
            }
            __syncthreads();
        }
    }
}

// ---------------- Aggregation (warp/node) + per-layer BN stat partials ----------------
__global__ __launch_bounds__(256) void agg_kernel(const float* __restrict__ bias, int n,
                                                  int layer) {
    __shared__ float red[8][256];
    int tid = threadIdx.x;
    int lane = tid & 31, wid = tid >> 5;
    float4 bv = *(const float4*)&bias[lane * 4];

    float ls0 = 0.f, ls1 = 0.f, ls2 = 0.f, ls3 = 0.f;
    float lq0 = 0.f, lq1 = 0.f, lq2 = 0.f, lq3 = 0.f;

    for (int node = blockIdx.x * 8 + wid; node < n; node += gridDim.x * 8) {
        int beg = __ldg(&g_rowptr[node]);
        int end = __ldg(&g_rowptr[node + 1]);
        float ax = 0.f, ay = 0.f, az = 0.f, aw = 0.f;
        int j = beg;
        for (; j + 3 < end; j += 4) {
            int c0 = __ldg(&g_cols[j]);
            int c1 = __ldg(&g_cols[j + 1]);
            int c2 = __ldg(&g_cols[j + 2]);
            int c3 = __ldg(&g_cols[j + 3]);
            float4 h0 = *(const float4*)&g_h[c0 * 128 + lane * 4];
            float4 h1 = *(const float4*)&g_h[c1 * 128 + lane * 4];
            float4 h2 = *(const float4*)&g_h[c2 * 128 + lane * 4];
            float4 h3 = *(const float4*)&g_h[c3 * 128 + lane * 4];
            ax += h0.x + h1.x + h2.x + h3.x;
            ay += h0.y + h1.y + h2.y + h3.y;
            az += h0.z + h1.z + h2.z + h3.z;
            aw += h0.w + h1.w + h2.w + h3.w;
        }
        for (; j < end; j++) {
            int c0 = __ldg(&g_cols[j]);
            float4 h0 = *(const float4*)&g_h[c0 * 128 + lane * 4];
            ax += h0.x; ay += h0.y; az += h0.z; aw += h0.w;
        }
        float4 hs = *(const float4*)&g_h[node * 128 + lane * 4];
        float dn = __ldg(&g_dis[node]);
        ax = dn * (ax + hs.x) + bv.x;
        ay = dn * (ay + hs.y) + bv.y;
        az = dn * (az + hs.z) + bv.z;
        aw = dn * (aw + hs.w) + bv.w;
        *(float4*)&g_agg[node * 128 + lane * 4] = make_float4(ax, ay, az, aw);

        ls0 += ax; ls1 += ay; ls2 += az; ls3 += aw;
        lq0 += ax * ax; lq1 += ay * ay; lq2 += az * az; lq3 += aw * aw;
    }

    int sbase = layer * 2 * DD;
    red[wid][lane * 4 + 0] = ls0;
    red[wid][lane * 4 + 1] = ls1;
    red[wid][lane * 4 + 2] = ls2;
    red[wid][lane * 4 + 3] = ls3;
    __syncthreads();
    float tot = 0.f;
    #pragma unroll
    for (int w = 0; w < 8; w++) tot += red[w][tid];
    if (tid < 128) atomicAdd(&g_stats[sbase + tid], tot);
    __syncthreads();
    red[wid][lane * 4 + 0] = lq0;
    red[wid][lane * 4 + 1] = lq1;
    red[wid][lane * 4 + 2] = lq2;
    red[wid][lane * 4 + 3] = lq3;
    __syncthreads();
    tot = 0.f;
    #pragma unroll
    for (int w = 0; w < 8; w++) tot += red[w][tid];
    if (tid < 128) atomicAdd(&g_stats[sbase + DD + tid], tot);
}

// ---------------- Final elementwise: out = x2 + bn_2(agg2), no relu ----------------
__global__ __launch_bounds__(256) void elem_final_kernel(float* __restrict__ out,
                                                         const float* __restrict__ gamma,
                                                         const float* __restrict__ beta,
                                                         int n4, float invn) {
    __shared__ float sscale[DD];
    __shared__ float sshift[DD];
    int tid = threadIdx.x;
    if (tid < DD) {
        int base = 2 * 2 * DD;
        float s  = g_stats[base + tid];
        float sq = g_stats[base + DD + tid];
        float mean = s * invn;
        float var  = sq * invn - mean * mean;
        float istd = rsqrtf(var + 1e-5f);
        float sc = gamma[tid] * istd;
        sscale[tid] = sc;
        sshift[tid] = beta[tid] - mean * sc;
    }
    __syncthreads();

    int idx = blockIdx.x * blockDim.x + tid;
    if (idx >= n4) return;
    int c4 = idx & 31;
    float4 sc = ((const float4*)sscale)[c4];
    float4 sh = ((const float4*)sshift)[c4];
    float4 a  = ((const float4*)g_agg)[idx];
    float4 r  = ((const float4*)g_x)[idx];
    float4 y;
    y.x = a.x * sc.x + sh.x + r.x;
    y.y = a.y * sc.y + sh.y + r.y;
    y.z = a.z * sc.z + sh.z + r.z;
    y.w = a.w * sc.w + sh.w + r.w;
    ((float4*)out)[idx] = y;
}

// ---------------- launch ----------------
extern "C" void kernel_launch(void* const* d_in, const int* in_sizes, int n_in,
                              void* d_out, int out_size) {
    const float* x      = (const float*)d_in[0];
    const int*   ei     = (const int*)d_in[1];
    const float* Ws     = (const float*)d_in[2];
    const float* bs     = (const float*)d_in[3];
    const float* gammas = (const float*)d_in[4];
    const float* betas  = (const float*)d_in[5];

    int n = in_sizes[0] / DD;   // 50000
    int e = in_sizes[1] / 2;    // 800000
    const int* src = ei;
    const int* dst = ei + e;

    csr_build_kernel<<<CSR_GRID, 256>>>(src, dst, n, e);
    wconv_kernel<<<(3 * DD * DD + 255) / 256, 256>>>(Ws);

    float invn = 1.0f / (float)n;
    int n4 = n * (DD / 4);
    int gemm_grid = (n + 63) / 64;
    int agg_grid = 1184;

    __nv_bfloat16 *wh_ptr, *wl_ptr;
    cudaGetSymbolAddress((void**)&wh_ptr, g_Whi);
    cudaGetSymbolAddress((void**)&wl_ptr, g_Wlo);

    for (int l = 0; l < 3; l++) {
        int mode = (l > 0) ? 1 : 0;
        int residual = (l > 1) ? 1 : 0;
        const float* gprev = gammas + (l > 0 ? (l - 1) : 0) * DD;
        const float* bprev = betas + (l > 0 ? (l - 1) : 0) * DD;
        gemm_wmma_kernel<<<gemm_grid, 128>>>(x, wh_ptr + l * DD * DD, wl_ptr + l * DD * DD,
                                             gprev, bprev, n, mode, residual, l, invn);
        agg_kernel<<<agg_grid, 256>>>(bs + l * DD, n, l);
    }
    elem_final_kernel<<<(n4 + 255) / 256, 256>>>((float*)d_out, gammas + 2 * DD,
                                                 betas + 2 * DD, n4, invn);
}